// round 7
// baseline (speedup 1.0000x reference)
#include <cuda_runtime.h>

#define NB    163842
#define CIN   64
#define COUT  64
#define KNB   7
#define PTOT  (KNB * NB)                 // 1,146,894
#define KTOT  (KNB * CIN)                // 448
#define KC    32
#define BATCH 2
#define GSTRIDE (64LL * (long long)PTOT) // per-batch floats

// Scratch 1: gathered A-matrix. In (c,p) order this IS the row-major (N,448)
// GEMM A: A[b].flat[n*448+k] = g[c*PTOT+p] with g[c*PTOT+p] = x[b,no[p],c].
__device__ float g_scratch[2LL * 64 * PTOT];
// Scratch 2: W duplicated-pair form: W2[k][2o] = W2[k][2o+1] = W[o][k].
__device__ float W2g[KTOT * 2 * COUT];

#define FMA_F32X2(d, a, b, c) \
    asm("fma.rn.f32x2 %0, %1, %2, %3;" : "=l"(d) : "l"(a), "l"(b), "l"(c))

// ---------------------------------------------------------------------------
// Kernel 1: gather + transpose, coalesced both sides, conflict-free phase B.
// Block: 128 consecutive p. Read x[b,no[p],0:64] (float4 rows, L2-cached:
// each vertex row is reused ~7x and x fits in L2), transpose via smem
// (stride 65), write g[c*PTOT+p] coalesced along p with streaming stores
// so the 587MB scratch stream does not evict x from L2.
// ---------------------------------------------------------------------------
__global__ __launch_bounds__(256) void gather_kernel(
    const float* __restrict__ x,
    const void* __restrict__ no_raw)
{
    __shared__ float s[128][65];          // 65: phase-B conflict-free
    __shared__ int   sidx[128];

    const int b   = blockIdx.y;
    const long long p0 = (long long)blockIdx.x * 128;
    const int tid = threadIdx.x;

    // Index width detect: int64 values < N have zero top words.
    const unsigned long long* no_u64 = (const unsigned long long*)no_raw;
    const bool is64 =
        (((no_u64[0] | no_u64[1] | no_u64[2] | no_u64[3]) >> 32) == 0ULL);

    if (tid < 128) {
        long long p = p0 + tid;
        int idx = 0;
        if (p < PTOT) {
            idx = is64 ? (int)((const long long*)no_raw)[p]
                       : ((const int*)no_raw)[p];
        }
        sidx[tid] = idx;
    }
    __syncthreads();

    const float4* xb4 = (const float4*)(x + (long long)b * NB * CIN);

    // Phase A: float4 global reads (default policy: keep x in L2),
    // scalar smem stores (2-way max).
    #pragma unroll
    for (int it = 0; it < (128 * 16) / 256; it++) {
        int i  = tid + it * 256;
        int pp = i >> 4, c4 = i & 15;
        float4 v = make_float4(0.f, 0.f, 0.f, 0.f);
        if (p0 + pp < PTOT) v = xb4[(long long)sidx[pp] * 16 + c4];
        s[pp][c4 * 4 + 0] = v.x;
        s[pp][c4 * 4 + 1] = v.y;
        s[pp][c4 * 4 + 2] = v.z;
        s[pp][c4 * 4 + 3] = v.w;
    }
    __syncthreads();

    // Phase B: conflict-free LDS down pp, coalesced streaming global writes.
    float* gb = g_scratch + (long long)b * GSTRIDE;
    #pragma unroll
    for (int it = 0; it < (128 * 64) / 256; it++) {
        int i  = tid + it * 256;
        int c  = i >> 7, pp = i & 127;
        long long p = p0 + pp;
        if (p < PTOT) __stcs(&gb[(long long)c * PTOT + p], s[pp][c]);
    }
}

// ---------------------------------------------------------------------------
// Kernel 2 (tiny): build duplicated-pair W2[k][2o]=W2[k][2o+1]=W[o][k].
// ---------------------------------------------------------------------------
__global__ __launch_bounds__(256) void w2_kernel(const float* __restrict__ W)
{
    int i = blockIdx.x * 256 + threadIdx.x;     // over 448*64
    if (i < KTOT * COUT) {
        int o = i & 63, k = i >> 6;
        float w = W[o * KTOT + k];
        *(float2*)&W2g[k * (2 * COUT) + 2 * o] = make_float2(w, w);
    }
}

// ---------------------------------------------------------------------------
// Kernel 3: out[b] = A[b](N,448) @ W^T + bias via FFMA2 (fma.rn.f32x2).
// 128 threads, block tile 128x64, thread tile 8 rows x 8 cols
// (= 4 f32x2 row-pairs x 8 pre-duplicated w columns). A reads are
// single-use -> __ldcs (evict-first).
// ---------------------------------------------------------------------------
__global__ __launch_bounds__(128, 4) void gemm_kernel(
    const float* __restrict__ bias,   // (64,)
    float* __restrict__ out)          // (B, N, 64)
{
    __shared__ float As[KC][132];     // [k][row], 528B rows (16B aligned)
    __shared__ float Ws2[KC][136];    // [k][2*o], 544B rows (16B aligned)

    const int b    = blockIdx.y;
    const int row0 = blockIdx.x * 128;
    const int tid  = threadIdx.x;
    const int ty   = tid >> 3;        // 0..15 -> rows ty*8..+7
    const int tx   = tid & 7;         // 0..7  -> cols tx*8..+7

    const float* gb = g_scratch + (long long)b * GSTRIDE;

    unsigned long long acc[4][8];     // [row-pair][col]
    #pragma unroll
    for (int r = 0; r < 4; r++)
        #pragma unroll
        for (int c = 0; c < 8; c++) acc[r][c] = 0ULL;

    for (int k0 = 0; k0 < KTOT; k0 += KC) {
        // Stage A: lane -> k (128B coalesced per 32 lanes), streaming loads.
        #pragma unroll
        for (int it = 0; it < (128 * KC) / 128; it++) {
            int i = tid + it * 128;
            int kk = i & (KC - 1), r = i >> 5;
            int row = row0 + r;
            As[kk][r] = (row < NB)
                ? __ldcs(&gb[(long long)row * KTOT + (k0 + kk)]) : 0.f;
        }
        // Stage W2 tile: 32 k-rows x 128 floats, float4 copies (L2-resident).
        #pragma unroll
        for (int it = 0; it < (KC * 32) / 128; it++) {
            int i = tid + it * 128;
            int c4 = i & 31, kk = i >> 5;
            *(float4*)&Ws2[kk][c4 * 4] =
                *(const float4*)&W2g[(k0 + kk) * 128 + c4 * 4];
        }
        __syncthreads();

        #pragma unroll 8
        for (int kk = 0; kk < KC; kk++) {
            ulonglong2 aA = *(const ulonglong2*)&As[kk][ty * 8];
            ulonglong2 aB = *(const ulonglong2*)&As[kk][ty * 8 + 4];
            unsigned long long ap[4] = {aA.x, aA.y, aB.x, aB.y};

            ulonglong2 w01 = *(const ulonglong2*)&Ws2[kk][tx * 16];
            ulonglong2 w23 = *(const ulonglong2*)&Ws2[kk][tx * 16 + 4];
            ulonglong2 w45 = *(const ulonglong2*)&Ws2[kk][tx * 16 + 8];
            ulonglong2 w67 = *(const ulonglong2*)&Ws2[kk][tx * 16 + 12];
            unsigned long long wp[8] = {w01.x, w01.y, w23.x, w23.y,
                                        w45.x, w45.y, w67.x, w67.y};

            #pragma unroll
            for (int r = 0; r < 4; r++)
                #pragma unroll
                for (int c = 0; c < 8; c++)
                    FMA_F32X2(acc[r][c], ap[r], wp[c], acc[r][c]);
        }
        __syncthreads();
    }

    // Epilogue: unpack f32x2 (x = even row, y = odd row), bias, store.
    const float4 bv0 = *(const float4*)&bias[tx * 8];
    const float4 bv1 = *(const float4*)&bias[tx * 8 + 4];
    const float bv[8] = {bv0.x, bv0.y, bv0.z, bv0.w,
                         bv1.x, bv1.y, bv1.z, bv1.w};
    #pragma unroll
    for (int r = 0; r < 4; r++) {
        #pragma unroll
        for (int half = 0; half < 2; half++) {
            int row = row0 + ty * 8 + 2 * r + half;
            if (row < NB) {
                float o[8];
                #pragma unroll
                for (int c = 0; c < 8; c++) {
                    float2 p = *(float2*)&acc[r][c];
                    o[c] = (half ? p.y : p.x) + bv[c];
                }
                float* po = out + ((long long)b * NB + row) * COUT + tx * 8;
                *(float4*)po       = make_float4(o[0], o[1], o[2], o[3]);
                *(float4*)(po + 4) = make_float4(o[4], o[5], o[6], o[7]);
            }
        }
    }
}

// ---------------------------------------------------------------------------
extern "C" void kernel_launch(void* const* d_in, const int* in_sizes, int n_in,
                              void* d_out, int out_size)
{
    const float* x    = (const float*)d_in[0];   // (B, N, 64)
    const float* W    = (const float*)d_in[1];   // (64, 448)
    const float* bias = (const float*)d_in[2];   // (64,)
    const void*  no   = d_in[3];                 // (7N,) int32 or int64
    float* out = (float*)d_out;                  // (B, N, 64)

    dim3 g1((PTOT + 127) / 128, BATCH);
    gather_kernel<<<g1, 256>>>(x, no);

    w2_kernel<<<(KTOT * COUT + 255) / 256, 256>>>(W);

    dim3 g2((NB + 127) / 128, BATCH);
    gemm_kernel<<<g2, 128>>>(bias, out);
}

// round 10
// speedup vs baseline: 2.1237x; 2.1237x over previous
#include <cuda_runtime.h>

#define NB    163842
#define CIN   64
#define COUT  64
#define KNB   7
#define PTOT  (KNB * NB)                 // 1,146,894
#define PSTRIDE 1146896                  // PTOT padded to /4 (16B-aligned planes)
#define KTOT  (KNB * CIN)                // 448
#define KC    32
#define BATCH 2
#define GSTRIDE (64LL * (long long)PSTRIDE) // per-batch floats

// Scratch 1: gathered matrix, padded planes: g[b][c][p] = x[b, no[p], c].
// Logical GEMM A row n: A[n][k] = g[c][p], f = n*448+k, c = f/PTOT, p = f%PTOT.
__device__ __align__(16) float g_scratch[2LL * 64 * PSTRIDE];
// Scratch 2: W in swizzled duplicated-pair form (see w2_kernel).
__device__ __align__(16) float W2g[KTOT * 128];

#define FMA_F32X2(d, a, b, c) \
    asm("fma.rn.f32x2 %0, %1, %2, %3;" : "=l"(d) : "l"(a), "l"(b), "l"(c))

// ---------------------------------------------------------------------------
// Kernel 1: gather + transpose, all stages 128-bit & conflict-free.
// Block: 128 consecutive p. smem = 64 c-rows x 32 units (16B), XOR-swizzled:
//   logical unit (c, pu) lives at phys unit c*32 + (pu ^ ((c>>2)&7)).
// Phase A: 4x coalesced LDG.128 of vertex rows, 4x4 register transpose,
//          4x STS.128 (8-lane phases hit distinct bank-quads).
// Phase B: LDS.128 (full row per warp) + contiguous STG.128 streaming.
// ---------------------------------------------------------------------------
__global__ __launch_bounds__(256) void gather_kernel(
    const float* __restrict__ x,
    const void* __restrict__ no_raw)
{
    __shared__ __align__(16) float su[64 * 128];   // 32KB
    __shared__ int sidx[128];

    const int b   = blockIdx.y;
    const long long p0 = (long long)blockIdx.x * 128;
    const int tid = threadIdx.x;

    // Index width detect: int64 values < N have zero top words.
    const unsigned long long* no_u64 = (const unsigned long long*)no_raw;
    const bool is64 =
        (((no_u64[0] | no_u64[1] | no_u64[2] | no_u64[3]) >> 32) == 0ULL);

    if (tid < 128) {
        long long p = p0 + tid;
        int idx = 0;
        if (p < PTOT) {
            idx = is64 ? (int)((const long long*)no_raw)[p]
                       : ((const int*)no_raw)[p];
        }
        sidx[tid] = idx;   // p >= PTOT -> vertex 0 (never stored to gmem)
    }
    __syncthreads();

    const float4* xb4 = (const float4*)(x + (long long)b * NB * CIN);
    float4* su4 = (float4*)su;

    // Phase A: 512 (c4, pp4) tiles, 2 per thread.
    #pragma unroll
    for (int it = 0; it < 2; it++) {
        int i   = tid + it * 256;
        int c4  = i & 15;          // 16B column group of x row
        int pp4 = i >> 4;          // group of 4 p-values (0..31)
        int pb  = pp4 * 4;

        float4 r0 = xb4[(long long)sidx[pb + 0] * 16 + c4];
        float4 r1 = xb4[(long long)sidx[pb + 1] * 16 + c4];
        float4 r2 = xb4[(long long)sidx[pb + 2] * 16 + c4];
        float4 r3 = xb4[(long long)sidx[pb + 3] * 16 + c4];

        // 4x4 transpose: column cc -> 4 consecutive p of channel c4*4+cc.
        float4 t0 = make_float4(r0.x, r1.x, r2.x, r3.x);
        float4 t1 = make_float4(r0.y, r1.y, r2.y, r3.y);
        float4 t2 = make_float4(r0.z, r1.z, r2.z, r3.z);
        float4 t3 = make_float4(r0.w, r1.w, r2.w, r3.w);

        int sw = pp4 ^ (c4 & 7);
        su4[(c4 * 4 + 0) * 32 + sw] = t0;
        su4[(c4 * 4 + 1) * 32 + sw] = t1;
        su4[(c4 * 4 + 2) * 32 + sw] = t2;
        su4[(c4 * 4 + 3) * 32 + sw] = t3;
    }
    __syncthreads();

    // Phase B: 2048 units, 8 per thread; warp covers one c-row (pu 0..31).
    float* gb = g_scratch + (long long)b * GSTRIDE;
    #pragma unroll
    for (int it = 0; it < 8; it++) {
        int i  = tid + it * 256;
        int pu = i & 31, c = i >> 5;
        float4 v = su4[c * 32 + (pu ^ ((c >> 2) & 7))];
        long long p = p0 + pu * 4;
        if (p < PTOT)   // tail spills only into the 16B plane pad
            __stcs((float4*)&gb[(long long)c * PSTRIDE + p], v);
    }
}

// ---------------------------------------------------------------------------
// Kernel 2 (tiny): build swizzled duplicated-pair W2.
// Layout per k (128 floats): for j in 0..3, tx in 0..7:
//   W2[k][j*32 + tx*4 + 0,1] = dup W[tx*8 + 2j    ][k]
//   W2[k][j*32 + tx*4 + 2,3] = dup W[tx*8 + 2j + 1][k]
// => math-loop load j of lane tx is at byte tx*16 + j*128: conflict-free.
// ---------------------------------------------------------------------------
__global__ __launch_bounds__(256) void w2_kernel(const float* __restrict__ W)
{
    int i = blockIdx.x * 256 + threadIdx.x;     // over 448*64
    if (i < KTOT * COUT) {
        int o = i & 63, k = i >> 6;
        int tx = o >> 3, c = o & 7, j = c >> 1, half = c & 1;
        float w = W[o * KTOT + k];
        *(float2*)&W2g[k * 128 + j * 32 + tx * 4 + half * 2]
            = make_float2(w, w);
    }
}

// ---------------------------------------------------------------------------
// Kernel 3: out[b,n,o] = bias[o] + sum_k W[o,k]*A[n,k] via FFMA2.
// 128 threads, block tile 128x64, thread tile 8 rows x 8 cols
// (4 f32x2 row-pairs x 8 pre-dup w cols). All inner LDS conflict-free.
// ---------------------------------------------------------------------------
__global__ __launch_bounds__(128, 4) void gemm_kernel(
    const float* __restrict__ bias,   // (64,)
    float* __restrict__ out)          // (B, N, 64)
{
    __shared__ __align__(16) float As[KC][132];   // [k][row], 528B rows
    __shared__ __align__(16) float Ws2[KC][128];  // [k][swizzled], 512B rows

    const int b    = blockIdx.y;
    const int row0 = blockIdx.x * 128;
    const int tid  = threadIdx.x;
    const int ty   = tid >> 3;        // 0..15 -> rows ty*8..+7
    const int tx   = tid & 7;         // 0..7  -> cols tx*8..+7

    const float* gb = g_scratch + (long long)b * GSTRIDE;

    unsigned long long acc[4][8];
    #pragma unroll
    for (int r = 0; r < 4; r++)
        #pragma unroll
        for (int c = 0; c < 8; c++) acc[r][c] = 0ULL;

    for (int k0 = 0; k0 < KTOT; k0 += KC) {
        // Stage A: lane -> k (coalesced 128B); padded-plane addressing.
        #pragma unroll
        for (int it = 0; it < (128 * KC) / 128; it++) {
            int i = tid + it * 128;
            int kk = i & (KC - 1), r = i >> 5;
            int row = row0 + r;
            float v = 0.f;
            if (row < NB) {
                unsigned f = (unsigned)row * (unsigned)KTOT
                           + (unsigned)(k0 + kk);
                unsigned c = f / (unsigned)PTOT;     // const-div -> mulhi
                unsigned p = f - c * (unsigned)PTOT;
                v = __ldcs(&gb[(long long)c * PSTRIDE + p]);
            }
            As[kk][r] = v;
        }
        // Stage W2 tile: flat copy, float4.
        #pragma unroll
        for (int it = 0; it < (KC * 32) / 128; it++) {
            int i = tid + it * 128;
            int c4 = i & 31, kk = i >> 5;
            *(float4*)&Ws2[kk][c4 * 4] =
                *(const float4*)&W2g[(k0 + kk) * 128 + c4 * 4];
        }
        __syncthreads();

        #pragma unroll 8
        for (int kk = 0; kk < KC; kk++) {
            ulonglong2 aA = *(const ulonglong2*)&As[kk][ty * 8];
            ulonglong2 aB = *(const ulonglong2*)&As[kk][ty * 8 + 4];
            unsigned long long ap[4] = {aA.x, aA.y, aB.x, aB.y};

            // Load j at byte tx*16 + j*128: conflict-free across lanes.
            ulonglong2 w0 = *(const ulonglong2*)&Ws2[kk][tx * 4];
            ulonglong2 w1 = *(const ulonglong2*)&Ws2[kk][32 + tx * 4];
            ulonglong2 w2 = *(const ulonglong2*)&Ws2[kk][64 + tx * 4];
            ulonglong2 w3 = *(const ulonglong2*)&Ws2[kk][96 + tx * 4];
            unsigned long long wp[8] = {w0.x, w0.y, w1.x, w1.y,
                                        w2.x, w2.y, w3.x, w3.y};

            #pragma unroll
            for (int r = 0; r < 4; r++)
                #pragma unroll
                for (int c = 0; c < 8; c++)
                    FMA_F32X2(acc[r][c], ap[r], wp[c], acc[r][c]);
        }
        __syncthreads();
    }

    // Epilogue: unpack f32x2 (x = even row, y = odd row), bias, store.
    const float4 bv0 = *(const float4*)&bias[tx * 8];
    const float4 bv1 = *(const float4*)&bias[tx * 8 + 4];
    const float bv[8] = {bv0.x, bv0.y, bv0.z, bv0.w,
                         bv1.x, bv1.y, bv1.z, bv1.w};
    #pragma unroll
    for (int r = 0; r < 4; r++) {
        #pragma unroll
        for (int half = 0; half < 2; half++) {
            int row = row0 + ty * 8 + 2 * r + half;
            if (row < NB) {
                float o[8];
                #pragma unroll
                for (int c = 0; c < 8; c++) {
                    float2 p = *(float2*)&acc[r][c];
                    o[c] = (half ? p.y : p.x) + bv[c];
                }
                float* po = out + ((long long)b * NB + row) * COUT + tx * 8;
                *(float4*)po       = make_float4(o[0], o[1], o[2], o[3]);
                *(float4*)(po + 4) = make_float4(o[4], o[5], o[6], o[7]);
            }
        }
    }
}

// ---------------------------------------------------------------------------
extern "C" void kernel_launch(void* const* d_in, const int* in_sizes, int n_in,
                              void* d_out, int out_size)
{
    const float* x    = (const float*)d_in[0];   // (B, N, 64)
    const float* W    = (const float*)d_in[1];   // (64, 448)
    const float* bias = (const float*)d_in[2];   // (64,)
    const void*  no   = d_in[3];                 // (7N,) int32 or int64
    float* out = (float*)d_out;                  // (B, N, 64)

    w2_kernel<<<(KTOT * COUT + 255) / 256, 256>>>(W);

    dim3 g1((PTOT + 127) / 128, BATCH);
    gather_kernel<<<g1, 256>>>(x, no);

    dim3 g2((NB + 127) / 128, BATCH);
    gemm_kernel<<<g2, 128>>>(bias, out);
}